// round 4
// baseline (speedup 1.0000x reference)
#include <cuda_runtime.h>
#include <math.h>

#define NB 2
#define SEQ 2048
#define HID 2048
#define NHQ 16
#define NHKV 8
#define HD 128
#define WIN 1024
#define MROWS (NB*SEQ)   // 4096

// ---------------- scratch (static device globals; no cudaMalloc allowed) ----
__device__ float g_q[(size_t)MROWS * NHQ * HD];     // 33.5 MB
__device__ float g_k[(size_t)MROWS * NHKV * HD];    // 16.8 MB
__device__ float g_v[(size_t)MROWS * NHKV * HD];    // 16.8 MB
__device__ float g_attn[(size_t)MROWS * NHQ * HD];  // 33.5 MB
__device__ float g_rope_cos[SEQ * 64];
__device__ float g_rope_sin[SEQ * 64];

// ---------------------------------------------------------------------------
__global__ void rope_table(float* __restrict__ ct, float* __restrict__ st)
{
    int idx = blockIdx.x * 256 + threadIdx.x;
    if (idx >= SEQ * 64) return;
    int pos = idx >> 6;
    int d   = idx & 63;
    double ang = (double)pos * pow(10000.0, -(double)d / 64.0);
    double s, c;
    sincos(ang, &s, &c);
    ct[idx] = (float)c;
    st[idx] = (float)s;
}

// ---------------------------------------------------------------------------
// tf32 helpers (fragment layout validated in gemm_tf32, R2)
// ---------------------------------------------------------------------------
__device__ __forceinline__ unsigned f2tf32(float x) {
    unsigned r;
    asm("cvt.rna.tf32.f32 %0, %1;" : "=r"(r) : "f"(x));
    return r;
}

__device__ __forceinline__ void mma_tf32(float c[4], const unsigned a[4],
                                         const unsigned b[2]) {
    asm volatile(
        "mma.sync.aligned.m16n8k8.row.col.f32.tf32.tf32.f32 "
        "{%0,%1,%2,%3}, {%4,%5,%6,%7}, {%8,%9}, {%0,%1,%2,%3};\n"
        : "+f"(c[0]), "+f"(c[1]), "+f"(c[2]), "+f"(c[3])
        : "r"(a[0]), "r"(a[1]), "r"(a[2]), "r"(a[3]), "r"(b[0]), "r"(b[1]));
}

// ---------------------------------------------------------------------------
// tf32 tensor-core GEMM (NT): C[M,N] = A[M,K] @ W[N,K]^T. (unchanged from R2)
// ---------------------------------------------------------------------------
#define SSTR 136

__global__ __launch_bounds__(256) void gemm_tf32(
    const float* __restrict__ A, const float* __restrict__ Wt,
    float* __restrict__ C, int M, int N, int K)
{
    __shared__ unsigned As[16][SSTR];
    __shared__ unsigned Bs[16][SSTR];
    const int tid  = threadIdx.x;
    const int lane = tid & 31;
    const int warp = tid >> 5;
    const int wm = warp >> 1;
    const int wn = warp & 1;
    const int gid = lane >> 2;
    const int tig = lane & 3;
    const int m0 = blockIdx.y << 7;
    const int n0 = blockIdx.x << 7;
    const int lr = tid >> 1;
    const int lc = (tid & 1) << 3;
    const float* Ag = A  + (size_t)(m0 + lr) * K + lc;
    const float* Wg = Wt + (size_t)(n0 + lr) * K + lc;

    float acc[2][8][4] = {};

    for (int k0 = 0; k0 < K; k0 += 16) {
        float4 a0 = *(const float4*)(Ag + k0);
        float4 a1 = *(const float4*)(Ag + k0 + 4);
        float4 b0 = *(const float4*)(Wg + k0);
        float4 b1 = *(const float4*)(Wg + k0 + 4);
        __syncthreads();
        As[lc+0][lr]=f2tf32(a0.x); As[lc+1][lr]=f2tf32(a0.y);
        As[lc+2][lr]=f2tf32(a0.z); As[lc+3][lr]=f2tf32(a0.w);
        As[lc+4][lr]=f2tf32(a1.x); As[lc+5][lr]=f2tf32(a1.y);
        As[lc+6][lr]=f2tf32(a1.z); As[lc+7][lr]=f2tf32(a1.w);
        Bs[lc+0][lr]=f2tf32(b0.x); Bs[lc+1][lr]=f2tf32(b0.y);
        Bs[lc+2][lr]=f2tf32(b0.z); Bs[lc+3][lr]=f2tf32(b0.w);
        Bs[lc+4][lr]=f2tf32(b1.x); Bs[lc+5][lr]=f2tf32(b1.y);
        Bs[lc+6][lr]=f2tf32(b1.z); Bs[lc+7][lr]=f2tf32(b1.w);
        __syncthreads();
        #pragma unroll
        for (int ks = 0; ks < 2; ks++) {
            const int kb = ks << 3;
            unsigned afr[2][4], bfr[8][2];
            #pragma unroll
            for (int mi = 0; mi < 2; mi++) {
                int mr = (wm << 5) + (mi << 4);
                afr[mi][0] = As[kb + tig    ][mr + gid];
                afr[mi][1] = As[kb + tig    ][mr + gid + 8];
                afr[mi][2] = As[kb + tig + 4][mr + gid];
                afr[mi][3] = As[kb + tig + 4][mr + gid + 8];
            }
            #pragma unroll
            for (int ni = 0; ni < 8; ni++) {
                int nc = (wn << 6) + (ni << 3);
                bfr[ni][0] = Bs[kb + tig    ][nc + gid];
                bfr[ni][1] = Bs[kb + tig + 4][nc + gid];
            }
            #pragma unroll
            for (int mi = 0; mi < 2; mi++)
                #pragma unroll
                for (int ni = 0; ni < 8; ni++)
                    mma_tf32(acc[mi][ni], afr[mi], bfr[ni]);
        }
    }
    #pragma unroll
    for (int mi = 0; mi < 2; mi++) {
        int r0 = m0 + (wm << 5) + (mi << 4) + gid;
        #pragma unroll
        for (int ni = 0; ni < 8; ni++) {
            int cc = n0 + (wn << 6) + (ni << 3) + (tig << 1);
            *(float2*)(C + (size_t)r0 * N + cc) =
                make_float2(acc[mi][ni][0], acc[mi][ni][1]);
            *(float2*)(C + (size_t)(r0 + 8) * N + cc) =
                make_float2(acc[mi][ni][2], acc[mi][ni][3]);
        }
    }
}

// ---------------------------------------------------------------------------
// RMSNorm + RoPE via table (unchanged)
// ---------------------------------------------------------------------------
__global__ __launch_bounds__(256) void norm_rope(
    float* __restrict__ x, const float* __restrict__ w, int n_heads,
    const float* __restrict__ ct, const float* __restrict__ st)
{
    int gw   = (blockIdx.x * 256 + threadIdx.x) >> 5;
    int lane = threadIdx.x & 31;
    if (gw >= MROWS * n_heads) return;
    int m = gw / n_heads;
    int h = gw - m * n_heads;
    int pos = m & (SEQ - 1);
    float* row = x + (size_t)m * (n_heads * HD) + h * HD;
    float x0 = row[lane], x1 = row[lane+32], x2 = row[lane+64], x3 = row[lane+96];
    float ss = x0*x0 + x1*x1 + x2*x2 + x3*x3;
    #pragma unroll
    for (int o = 16; o; o >>= 1) ss += __shfl_xor_sync(0xffffffffu, ss, o);
    float rstd = rsqrtf(ss * (1.0f / HD) + 1e-6f);
    float y0 = x0 * rstd * (1.f + w[lane]);
    float y1 = x1 * rstd * (1.f + w[lane+32]);
    float y2 = x2 * rstd * (1.f + w[lane+64]);
    float y3 = x3 * rstd * (1.f + w[lane+96]);
    float c0 = ct[pos*64 + lane],      s0 = st[pos*64 + lane];
    float c1 = ct[pos*64 + lane + 32], s1 = st[pos*64 + lane + 32];
    row[lane]      = y0 * c0 - y2 * s0;
    row[lane+64]   = y2 * c0 + y0 * s0;
    row[lane+32]   = y1 * c1 - y3 * s1;
    row[lane+96]   = y3 * c1 + y1 * s1;
}

// ---------------------------------------------------------------------------
// Flash attention, tf32 mma. R4: Q staging buffer ALIASES the K/V smem region
// (Q fragments become register-resident before the mainloop), cutting smem
// 121KB -> 87.8KB => 2 CTAs/SM. __launch_bounds__(256,2) caps regs at 128.
// ---------------------------------------------------------------------------
#define FBQ 64
#define FBK 64
#define QSTR 132
#define KSTR 72
#define VSTR 136
#define PSTR 68
#define FLASH_WORDS (128*KSTR + 64*VSTR + 64*PSTR + 3*64)   // 22464
#define FLASH_BYTES (FLASH_WORDS * 4)                       // 89856

__global__ __launch_bounds__(256, 2) void flash_tf32(
    const float* __restrict__ q, const float* __restrict__ k,
    const float* __restrict__ v, float* __restrict__ o)
{
    extern __shared__ unsigned smu[];
    unsigned* KsT = smu;                      // [128][KSTR] d-major tf32
    unsigned* Vs  = KsT + 128 * KSTR;         // [64][VSTR]  tf32
    float*    Ss  = (float*)(Vs + 64 * VSTR); // [64][PSTR]  scores -> P tf32
    float* m_s = Ss + 64 * PSTR;
    float* l_s = m_s + 64;
    float* c_s = l_s + 64;
    unsigned* Psu = (unsigned*)Ss;
    unsigned* Qstage = smu;                   // ALIAS: [64][QSTR] (8448 w < 17920)

    const int tid  = threadIdx.x;
    const int lane = tid & 31;
    const int warp = tid >> 5;
    const int wm = warp >> 1;        // 0..3
    const int wn = warp & 1;         // 0..1
    const int g  = lane >> 2;        // 0..7
    const int t  = lane & 3;         // 0..3
    const int mrow = wm << 4;

    const int q0 = blockIdx.x * FBQ;
    const int h  = blockIdx.y;
    const int b  = blockIdx.z;
    const int hk = h >> 1;
    const float* qbase = q + (size_t)b * SEQ * (NHQ  * HD) + h  * HD;
    const float* kbase = k + (size_t)b * SEQ * (NHKV * HD) + hk * HD;
    const float* vbase = v + (size_t)b * SEQ * (NHKV * HD) + hk * HD;
    const float scale = 0.08838834764831845f;   // 1/sqrt(128), folded into Q

    // ---- stage Q (scaled, tf32) into aliased smem ----
    #pragma unroll
    for (int rep = 0; rep < 8; rep++) {
        int idx = rep * 256 + tid;
        int r   = idx >> 5;
        int dc  = (idx & 31) << 2;
        float4 va = *(const float4*)(qbase + (size_t)(q0 + r) * (NHQ * HD) + dc);
        unsigned* dst = Qstage + r * QSTR + dc;
        dst[0] = f2tf32(va.x * scale); dst[1] = f2tf32(va.y * scale);
        dst[2] = f2tf32(va.z * scale); dst[3] = f2tf32(va.w * scale);
    }
    if (tid < 64) { m_s[tid] = -1e30f; l_s[tid] = 0.f; }
    __syncthreads();

    // ---- extract persistent Q fragments, then release the staging region ----
    unsigned qf[16][4];
    #pragma unroll
    for (int kc = 0; kc < 16; kc++) {
        int kb = kc << 3;
        qf[kc][0] = Qstage[(mrow + g    ) * QSTR + kb + t];
        qf[kc][1] = Qstage[(mrow + g + 8) * QSTR + kb + t];
        qf[kc][2] = Qstage[(mrow + g    ) * QSTR + kb + t + 4];
        qf[kc][3] = Qstage[(mrow + g + 8) * QSTR + kb + t + 4];
    }
    __syncthreads();   // all reads of Qstage done before K/V overwrite it

    float oacc[8][4] = {};
    const int sm_r = tid >> 2;
    const int sm_g = tid & 3;

    int jlo = q0 - (WIN - 1); if (jlo < 0) jlo = 0;
    const int jstart = jlo & ~(FBK - 1);

    for (int j0 = jstart; j0 <= q0; j0 += FBK) {
        __syncthreads();
        // ---- K transpose load (d-major) + V load, tf32 ----
        {
            int r  = tid >> 2;
            int c4 = (tid & 3) << 2;
            #pragma unroll
            for (int sub = 0; sub < 8; sub++) {
                float4 kv = *(const float4*)(kbase + (size_t)(j0 + r) * (NHKV * HD) + sub * 16 + c4);
                int dbase = sub * 16 + c4;
                KsT[(dbase+0)*KSTR + r] = f2tf32(kv.x);
                KsT[(dbase+1)*KSTR + r] = f2tf32(kv.y);
                KsT[(dbase+2)*KSTR + r] = f2tf32(kv.z);
                KsT[(dbase+3)*KSTR + r] = f2tf32(kv.w);
            }
        }
        #pragma unroll
        for (int rep = 0; rep < 8; rep++) {
            int idx = rep * 256 + tid;
            int r   = idx >> 5;
            int dc  = (idx & 31) << 2;
            float4 vv = *(const float4*)(vbase + (size_t)(j0 + r) * (NHKV * HD) + dc);
            unsigned* dst = Vs + r * VSTR + dc;
            dst[0] = f2tf32(vv.x); dst[1] = f2tf32(vv.y);
            dst[2] = f2tf32(vv.z); dst[3] = f2tf32(vv.w);
        }
        __syncthreads();

        // ---- S = Q K^T (warp tile 16x32) ----
        float sacc[4][4] = {};
        #pragma unroll
        for (int kc = 0; kc < 16; kc++) {
            int kb = kc << 3;
            unsigned bf[4][2];
            #pragma unroll
            for (int ni = 0; ni < 4; ni++) {
                int jn = (wn << 5) + (ni << 3);
                bf[ni][0] = KsT[(kb + t    ) * KSTR + jn + g];
                bf[ni][1] = KsT[(kb + t + 4) * KSTR + jn + g];
            }
            #pragma unroll
            for (int ni = 0; ni < 4; ni++)
                mma_tf32(sacc[ni], qf[kc], bf[ni]);
        }
        #pragma unroll
        for (int ni = 0; ni < 4; ni++) {
            int jn = (wn << 5) + (ni << 3) + (t << 1);
            Ss[(mrow + g    ) * PSTR + jn]     = sacc[ni][0];
            Ss[(mrow + g    ) * PSTR + jn + 1] = sacc[ni][1];
            Ss[(mrow + g + 8) * PSTR + jn]     = sacc[ni][2];
            Ss[(mrow + g + 8) * PSTR + jn + 1] = sacc[ni][3];
        }
        __syncthreads();

        // ---- online softmax (4 threads/row), mask here ----
        {
            int qi = q0 + sm_r;
            float sv[16];
            float mx = -1e30f;
            #pragma unroll
            for (int u = 0; u < 16; u++) {
                int kj = j0 + sm_g * 16 + u;
                float s = Ss[sm_r * PSTR + sm_g * 16 + u];
                bool valid = (kj <= qi) && (kj > qi - WIN);
                sv[u] = valid ? s : -1e30f;
                mx = fmaxf(mx, sv[u]);
            }
            mx = fmaxf(mx, __shfl_xor_sync(0xffffffffu, mx, 1));
            mx = fmaxf(mx, __shfl_xor_sync(0xffffffffu, mx, 2));
            float m_old = m_s[sm_r];
            float m_new = fmaxf(m_old, mx);
            float corr  = __expf(m_old - m_new);
            float psum  = 0.f;
            #pragma unroll
            for (int u = 0; u < 16; u++) {
                float p = (sv[u] > -1e29f) ? __expf(sv[u] - m_new) : 0.f;
                Psu[sm_r * PSTR + sm_g * 16 + u] = f2tf32(p);
                psum += p;
            }
            psum += __shfl_xor_sync(0xffffffffu, psum, 1);
            psum += __shfl_xor_sync(0xffffffffu, psum, 2);
            if (sm_g == 0) {
                m_s[sm_r] = m_new;
                c_s[sm_r] = corr;
                l_s[sm_r] = l_s[sm_r] * corr + psum;
            }
        }
        __syncthreads();

        // ---- O = O*corr + P V (warp tile 16x64) ----
        {
            float cl = c_s[mrow + g];
            float ch = c_s[mrow + g + 8];
            #pragma unroll
            for (int ni = 0; ni < 8; ni++) {
                oacc[ni][0] *= cl; oacc[ni][1] *= cl;
                oacc[ni][2] *= ch; oacc[ni][3] *= ch;
            }
            #pragma unroll
            for (int kc = 0; kc < 8; kc++) {
                int kb = kc << 3;
                unsigned af[4];
                af[0] = Psu[(mrow + g    ) * PSTR + kb + t];
                af[1] = Psu[(mrow + g + 8) * PSTR + kb + t];
                af[2] = Psu[(mrow + g    ) * PSTR + kb + t + 4];
                af[3] = Psu[(mrow + g + 8) * PSTR + kb + t + 4];
                #pragma unroll
                for (int ni = 0; ni < 8; ni++) {
                    int dn = (wn << 6) + (ni << 3);
                    unsigned bb[2];
                    bb[0] = Vs[(kb + t    ) * VSTR + dn + g];
                    bb[1] = Vs[(kb + t + 4) * VSTR + dn + g];
                    mma_tf32(oacc[ni], af, bb);
                }
            }
        }
    }

    // ---- epilogue: divide by l, store ----
    float il = 1.0f / l_s[mrow + g];
    float ih = 1.0f / l_s[mrow + g + 8];
    float* obase = o + (size_t)b * SEQ * (NHQ * HD) + h * HD;
    int rlo = q0 + mrow + g;
    int rhi = rlo + 8;
    #pragma unroll
    for (int ni = 0; ni < 8; ni++) {
        int dn = (wn << 6) + (ni << 3) + (t << 1);
        *(float2*)(obase + (size_t)rlo * (NHQ * HD) + dn) =
            make_float2(oacc[ni][0] * il, oacc[ni][1] * il);
        *(float2*)(obase + (size_t)rhi * (NHQ * HD) + dn) =
            make_float2(oacc[ni][2] * ih, oacc[ni][3] * ih);
    }
}

// ---------------------------------------------------------------------------
extern "C" void kernel_launch(void* const* d_in, const int* in_sizes, int n_in,
                              void* d_out, int out_size)
{
    const float* hidden = (const float*)d_in[0];
    const float* wq = (const float*)d_in[1];
    const float* wk = (const float*)d_in[2];
    const float* wv = (const float*)d_in[3];
    const float* wo = (const float*)d_in[4];
    const float* qw = (const float*)d_in[5];
    const float* kw = (const float*)d_in[6];
    float* out = (float*)d_out;

    float *q, *k, *v, *attn, *ct, *st;
    cudaGetSymbolAddress((void**)&q,    g_q);
    cudaGetSymbolAddress((void**)&k,    g_k);
    cudaGetSymbolAddress((void**)&v,    g_v);
    cudaGetSymbolAddress((void**)&attn, g_attn);
    cudaGetSymbolAddress((void**)&ct,   g_rope_cos);
    cudaGetSymbolAddress((void**)&st,   g_rope_sin);

    cudaFuncSetAttribute(flash_tf32, cudaFuncAttributeMaxDynamicSharedMemorySize,
                         FLASH_BYTES);

    rope_table<<<(SEQ*64 + 255) / 256, 256>>>(ct, st);
    gemm_tf32<<<dim3((NHQ*HD)/128,  MROWS/128), 256>>>(hidden, wq, q, MROWS, NHQ*HD,  HID);
    gemm_tf32<<<dim3((NHKV*HD)/128, MROWS/128), 256>>>(hidden, wk, k, MROWS, NHKV*HD, HID);
    gemm_tf32<<<dim3((NHKV*HD)/128, MROWS/128), 256>>>(hidden, wv, v, MROWS, NHKV*HD, HID);
    norm_rope<<<(MROWS*NHQ *32 + 255) / 256, 256>>>(q, qw, NHQ,  ct, st);
    norm_rope<<<(MROWS*NHKV*32 + 255) / 256, 256>>>(k, kw, NHKV, ct, st);
    flash_tf32<<<dim3(SEQ/FBQ, NHQ, NB), 256, FLASH_BYTES>>>(q, k, v, attn);
    gemm_tf32<<<dim3(HID/128, MROWS/128), 256>>>(attn, wo, out, MROWS, HID, NHQ*HD);
}

// round 5
// speedup vs baseline: 1.0537x; 1.0537x over previous
#include <cuda_runtime.h>
#include <math.h>

#define NB 2
#define SEQ 2048
#define HID 2048
#define NHQ 16
#define NHKV 8
#define HD 128
#define WIN 1024
#define MROWS (NB*SEQ)   // 4096

// ---------------- scratch (static device globals; no cudaMalloc allowed) ----
__device__ float g_q[(size_t)MROWS * NHQ * HD];     // 33.5 MB
__device__ float g_k[(size_t)MROWS * NHKV * HD];    // 16.8 MB
__device__ float g_v[(size_t)MROWS * NHKV * HD];    // 16.8 MB
__device__ float g_attn[(size_t)MROWS * NHQ * HD];  // 33.5 MB
__device__ float g_rope_cos[SEQ * 64];
__device__ float g_rope_sin[SEQ * 64];

// ---------------------------------------------------------------------------
__global__ void rope_table(float* __restrict__ ct, float* __restrict__ st)
{
    int idx = blockIdx.x * 256 + threadIdx.x;
    if (idx >= SEQ * 64) return;
    int pos = idx >> 6;
    int d   = idx & 63;
    double ang = (double)pos * pow(10000.0, -(double)d / 64.0);
    double s, c;
    sincos(ang, &s, &c);
    ct[idx] = (float)c;
    st[idx] = (float)s;
}

// ---------------------------------------------------------------------------
__device__ __forceinline__ unsigned f2tf32(float x) {
    unsigned r;
    asm("cvt.rna.tf32.f32 %0, %1;" : "=r"(r) : "f"(x));
    return r;
}

__device__ __forceinline__ void mma_tf32(float c[4], const unsigned a[4],
                                         const unsigned b[2]) {
    asm volatile(
        "mma.sync.aligned.m16n8k8.row.col.f32.tf32.tf32.f32 "
        "{%0,%1,%2,%3}, {%4,%5,%6,%7}, {%8,%9}, {%0,%1,%2,%3};\n"
        : "+f"(c[0]), "+f"(c[1]), "+f"(c[2]), "+f"(c[3])
        : "r"(a[0]), "r"(a[1]), "r"(a[2]), "r"(a[3]), "r"(b[0]), "r"(b[1]));
}

// ---------------------------------------------------------------------------
// tf32 tensor-core GEMM (NT), unchanged from R2.
// ---------------------------------------------------------------------------
#define SSTR 136

__global__ __launch_bounds__(256) void gemm_tf32(
    const float* __restrict__ A, const float* __restrict__ Wt,
    float* __restrict__ C, int M, int N, int K)
{
    __shared__ unsigned As[16][SSTR];
    __shared__ unsigned Bs[16][SSTR];
    const int tid  = threadIdx.x;
    const int lane = tid & 31;
    const int warp = tid >> 5;
    const int wm = warp >> 1;
    const int wn = warp & 1;
    const int gid = lane >> 2;
    const int tig = lane & 3;
    const int m0 = blockIdx.y << 7;
    const int n0 = blockIdx.x << 7;
    const int lr = tid >> 1;
    const int lc = (tid & 1) << 3;
    const float* Ag = A  + (size_t)(m0 + lr) * K + lc;
    const float* Wg = Wt + (size_t)(n0 + lr) * K + lc;

    float acc[2][8][4] = {};

    for (int k0 = 0; k0 < K; k0 += 16) {
        float4 a0 = *(const float4*)(Ag + k0);
        float4 a1 = *(const float4*)(Ag + k0 + 4);
        float4 b0 = *(const float4*)(Wg + k0);
        float4 b1 = *(const float4*)(Wg + k0 + 4);
        __syncthreads();
        As[lc+0][lr]=f2tf32(a0.x); As[lc+1][lr]=f2tf32(a0.y);
        As[lc+2][lr]=f2tf32(a0.z); As[lc+3][lr]=f2tf32(a0.w);
        As[lc+4][lr]=f2tf32(a1.x); As[lc+5][lr]=f2tf32(a1.y);
        As[lc+6][lr]=f2tf32(a1.z); As[lc+7][lr]=f2tf32(a1.w);
        Bs[lc+0][lr]=f2tf32(b0.x); Bs[lc+1][lr]=f2tf32(b0.y);
        Bs[lc+2][lr]=f2tf32(b0.z); Bs[lc+3][lr]=f2tf32(b0.w);
        Bs[lc+4][lr]=f2tf32(b1.x); Bs[lc+5][lr]=f2tf32(b1.y);
        Bs[lc+6][lr]=f2tf32(b1.z); Bs[lc+7][lr]=f2tf32(b1.w);
        __syncthreads();
        #pragma unroll
        for (int ks = 0; ks < 2; ks++) {
            const int kb = ks << 3;
            unsigned afr[2][4], bfr[8][2];
            #pragma unroll
            for (int mi = 0; mi < 2; mi++) {
                int mr = (wm << 5) + (mi << 4);
                afr[mi][0] = As[kb + tig    ][mr + gid];
                afr[mi][1] = As[kb + tig    ][mr + gid + 8];
                afr[mi][2] = As[kb + tig + 4][mr + gid];
                afr[mi][3] = As[kb + tig + 4][mr + gid + 8];
            }
            #pragma unroll
            for (int ni = 0; ni < 8; ni++) {
                int nc = (wn << 6) + (ni << 3);
                bfr[ni][0] = Bs[kb + tig    ][nc + gid];
                bfr[ni][1] = Bs[kb + tig + 4][nc + gid];
            }
            #pragma unroll
            for (int mi = 0; mi < 2; mi++)
                #pragma unroll
                for (int ni = 0; ni < 8; ni++)
                    mma_tf32(acc[mi][ni], afr[mi], bfr[ni]);
        }
    }
    #pragma unroll
    for (int mi = 0; mi < 2; mi++) {
        int r0 = m0 + (wm << 5) + (mi << 4) + gid;
        #pragma unroll
        for (int ni = 0; ni < 8; ni++) {
            int cc = n0 + (wn << 6) + (ni << 3) + (tig << 1);
            *(float2*)(C + (size_t)r0 * N + cc) =
                make_float2(acc[mi][ni][0], acc[mi][ni][1]);
            *(float2*)(C + (size_t)(r0 + 8) * N + cc) =
                make_float2(acc[mi][ni][2], acc[mi][ni][3]);
        }
    }
}

// ---------------------------------------------------------------------------
// RMSNorm + RoPE via table (unchanged)
// ---------------------------------------------------------------------------
__global__ __launch_bounds__(256) void norm_rope(
    float* __restrict__ x, const float* __restrict__ w, int n_heads,
    const float* __restrict__ ct, const float* __restrict__ st)
{
    int gw   = (blockIdx.x * 256 + threadIdx.x) >> 5;
    int lane = threadIdx.x & 31;
    if (gw >= MROWS * n_heads) return;
    int m = gw / n_heads;
    int h = gw - m * n_heads;
    int pos = m & (SEQ - 1);
    float* row = x + (size_t)m * (n_heads * HD) + h * HD;
    float x0 = row[lane], x1 = row[lane+32], x2 = row[lane+64], x3 = row[lane+96];
    float ss = x0*x0 + x1*x1 + x2*x2 + x3*x3;
    #pragma unroll
    for (int o = 16; o; o >>= 1) ss += __shfl_xor_sync(0xffffffffu, ss, o);
    float rstd = rsqrtf(ss * (1.0f / HD) + 1e-6f);
    float y0 = x0 * rstd * (1.f + w[lane]);
    float y1 = x1 * rstd * (1.f + w[lane+32]);
    float y2 = x2 * rstd * (1.f + w[lane+64]);
    float y3 = x3 * rstd * (1.f + w[lane+96]);
    float c0 = ct[pos*64 + lane],      s0 = st[pos*64 + lane];
    float c1 = ct[pos*64 + lane + 32], s1 = st[pos*64 + lane + 32];
    row[lane]      = y0 * c0 - y2 * s0;
    row[lane+64]   = y2 * c0 + y0 * s0;
    row[lane+32]   = y1 * c1 - y3 * s1;
    row[lane+96]   = y3 * c1 + y1 * s1;
}

// ---------------------------------------------------------------------------
// Flash attention R5: BQ=128, 8 warps, each warp owns 16 rows x full 64-key
// tile. Softmax + stats fully in registers (quad shfl reductions); P converted
// acc->A-fragment via intra-quad shuffles. 2 barriers/tile. K/V traffic per
// query halved vs BQ=64.
// ---------------------------------------------------------------------------
#define FBQ 128
#define FBK 64
#define QSTR 132   // = 4 mod 32 -> Q frag LDS banks 4g+t (conflict-free)
#define KSTR 72    // = 8 mod 32 -> K frag LDS banks 8t+g
#define VSTR 136   // = 8 mod 32 -> V frag LDS banks 8t+g
#define FLASH_WORDS (128*QSTR + 128*KSTR + 64*VSTR)   // 34816
#define FLASH_BYTES (FLASH_WORDS * 4)                 // 139264

__global__ __launch_bounds__(256) void flash_tf32(
    const float* __restrict__ q, const float* __restrict__ k,
    const float* __restrict__ v, float* __restrict__ o)
{
    extern __shared__ unsigned smu[];
    unsigned* Qs  = smu;                 // [128][QSTR] tf32 (pre-scaled)
    unsigned* KsT = Qs + 128 * QSTR;     // [128][KSTR] d-major tf32
    unsigned* Vs  = KsT + 128 * KSTR;    // [64][VSTR]  tf32

    const int tid  = threadIdx.x;
    const int lane = tid & 31;
    const int warp = tid >> 5;           // 0..7
    const int g    = lane >> 2;          // 0..7
    const int t    = lane & 3;           // 0..3
    const int mrow = warp << 4;          // warp's 16-row block

    const int q0 = blockIdx.x * FBQ;
    const int h  = blockIdx.y;
    const int b  = blockIdx.z;
    const int hk = h >> 1;               // GQA repeat_interleave
    const float* qbase = q + (size_t)b * SEQ * (NHQ  * HD) + h  * HD;
    const float* kbase = k + (size_t)b * SEQ * (NHKV * HD) + hk * HD;
    const float* vbase = v + (size_t)b * SEQ * (NHKV * HD) + hk * HD;
    const float scale = 0.08838834764831845f;   // 1/sqrt(128), folded into Q

    // ---- load Q tile (128 rows), scaled tf32 ----
    #pragma unroll
    for (int rep = 0; rep < 16; rep++) {
        int idx = rep * 256 + tid;          // float4 index, 4096 total
        int r   = idx >> 5;
        int dc  = (idx & 31) << 2;
        float4 va = *(const float4*)(qbase + (size_t)(q0 + r) * (NHQ * HD) + dc);
        unsigned* dst = Qs + r * QSTR + dc;
        dst[0] = f2tf32(va.x * scale); dst[1] = f2tf32(va.y * scale);
        dst[2] = f2tf32(va.z * scale); dst[3] = f2tf32(va.w * scale);
    }

    float oacc[16][4] = {};
    float m_lo = -1e30f, m_hi = -1e30f, l_lo = 0.f, l_hi = 0.f;
    const int qi_lo = q0 + mrow + g;
    const int qi_hi = qi_lo + 8;

    int jlo = q0 - (WIN - 1); if (jlo < 0) jlo = 0;
    const int jstart = jlo & ~(FBK - 1);

    const int src0 = (lane & ~3) | (t >> 1);   // quad lane holding col t
    const int src1 = src0 + 2;                 // quad lane holding col t+4
    const bool odd = t & 1;

    for (int j0 = jstart; j0 < q0 + FBQ; j0 += FBK) {
        __syncthreads();   // previous tile's smem reads done (also covers Q load on iter 0)
        // ---- K transpose load (d-major) + V load, tf32 ----
        {
            int r  = tid >> 2;                 // 0..63 key
            int c4 = (tid & 3) << 2;
            #pragma unroll
            for (int sub = 0; sub < 8; sub++) {
                float4 kv = *(const float4*)(kbase + (size_t)(j0 + r) * (NHKV * HD) + sub * 16 + c4);
                int dbase = sub * 16 + c4;
                KsT[(dbase+0)*KSTR + r] = f2tf32(kv.x);
                KsT[(dbase+1)*KSTR + r] = f2tf32(kv.y);
                KsT[(dbase+2)*KSTR + r] = f2tf32(kv.z);
                KsT[(dbase+3)*KSTR + r] = f2tf32(kv.w);
            }
        }
        #pragma unroll
        for (int rep = 0; rep < 8; rep++) {
            int idx = rep * 256 + tid;
            int r   = idx >> 5;
            int dc  = (idx & 31) << 2;
            float4 vv = *(const float4*)(vbase + (size_t)(j0 + r) * (NHKV * HD) + dc);
            unsigned* dst = Vs + r * VSTR + dc;
            dst[0] = f2tf32(vv.x); dst[1] = f2tf32(vv.y);
            dst[2] = f2tf32(vv.z); dst[3] = f2tf32(vv.w);
        }
        __syncthreads();

        // ---- S = Q K^T  (warp tile 16 x 64) ----
        float sacc[8][4] = {};
        #pragma unroll
        for (int kc = 0; kc < 16; kc++) {
            int kb = kc << 3;
            unsigned qa[4];
            qa[0] = Qs[(mrow + g    ) * QSTR + kb + t];
            qa[1] = Qs[(mrow + g + 8) * QSTR + kb + t];
            qa[2] = Qs[(mrow + g    ) * QSTR + kb + t + 4];
            qa[3] = Qs[(mrow + g + 8) * QSTR + kb + t + 4];
            unsigned bb[8][2];
            #pragma unroll
            for (int ni = 0; ni < 8; ni++) {
                bb[ni][0] = KsT[(kb + t    ) * KSTR + (ni << 3) + g];
                bb[ni][1] = KsT[(kb + t + 4) * KSTR + (ni << 3) + g];
            }
            #pragma unroll
            for (int ni = 0; ni < 8; ni++)
                mma_tf32(sacc[ni], qa, bb[ni]);
        }

        // ---- mask + row max (registers + quad shfl) ----
        float mx_lo = -1e30f, mx_hi = -1e30f;
        #pragma unroll
        for (int ni = 0; ni < 8; ni++) {
            int c0 = j0 + (ni << 3) + (t << 1);
            int c1 = c0 + 1;
            if (!((c0 <= qi_lo) && (c0 > qi_lo - WIN))) sacc[ni][0] = -1e30f;
            if (!((c1 <= qi_lo) && (c1 > qi_lo - WIN))) sacc[ni][1] = -1e30f;
            if (!((c0 <= qi_hi) && (c0 > qi_hi - WIN))) sacc[ni][2] = -1e30f;
            if (!((c1 <= qi_hi) && (c1 > qi_hi - WIN))) sacc[ni][3] = -1e30f;
            mx_lo = fmaxf(mx_lo, fmaxf(sacc[ni][0], sacc[ni][1]));
            mx_hi = fmaxf(mx_hi, fmaxf(sacc[ni][2], sacc[ni][3]));
        }
        mx_lo = fmaxf(mx_lo, __shfl_xor_sync(0xffffffffu, mx_lo, 1));
        mx_lo = fmaxf(mx_lo, __shfl_xor_sync(0xffffffffu, mx_lo, 2));
        mx_hi = fmaxf(mx_hi, __shfl_xor_sync(0xffffffffu, mx_hi, 1));
        mx_hi = fmaxf(mx_hi, __shfl_xor_sync(0xffffffffu, mx_hi, 2));

        float mnl = fmaxf(m_lo, mx_lo);
        float mnh = fmaxf(m_hi, mx_hi);
        float cl  = __expf(m_lo - mnl);
        float ch  = __expf(m_hi - mnh);
        m_lo = mnl; m_hi = mnh;

        // ---- exp -> P (tf32 bits in registers), row sums ----
        float ps_lo = 0.f, ps_hi = 0.f;
        unsigned pf[8][4];
        #pragma unroll
        for (int ni = 0; ni < 8; ni++) {
            float p0 = (sacc[ni][0] > -1e29f) ? __expf(sacc[ni][0] - mnl) : 0.f;
            float p1 = (sacc[ni][1] > -1e29f) ? __expf(sacc[ni][1] - mnl) : 0.f;
            float p2 = (sacc[ni][2] > -1e29f) ? __expf(sacc[ni][2] - mnh) : 0.f;
            float p3 = (sacc[ni][3] > -1e29f) ? __expf(sacc[ni][3] - mnh) : 0.f;
            ps_lo += p0 + p1;
            ps_hi += p2 + p3;
            pf[ni][0] = f2tf32(p0); pf[ni][1] = f2tf32(p1);
            pf[ni][2] = f2tf32(p2); pf[ni][3] = f2tf32(p3);
        }
        ps_lo += __shfl_xor_sync(0xffffffffu, ps_lo, 1);
        ps_lo += __shfl_xor_sync(0xffffffffu, ps_lo, 2);
        ps_hi += __shfl_xor_sync(0xffffffffu, ps_hi, 1);
        ps_hi += __shfl_xor_sync(0xffffffffu, ps_hi, 2);
        l_lo = l_lo * cl + ps_lo;
        l_hi = l_hi * ch + ps_hi;

        // ---- rescale O accumulator ----
        #pragma unroll
        for (int n2 = 0; n2 < 16; n2++) {
            oacc[n2][0] *= cl; oacc[n2][1] *= cl;
            oacc[n2][2] *= ch; oacc[n2][3] *= ch;
        }

        // ---- O += P V  (acc->A-frag via quad shuffles, warp tile 16x128) ----
        #pragma unroll
        for (int kc = 0; kc < 8; kc++) {
            unsigned e0 = __shfl_sync(0xffffffffu, pf[kc][0], src0);
            unsigned o0 = __shfl_sync(0xffffffffu, pf[kc][1], src0);
            unsigned e1 = __shfl_sync(0xffffffffu, pf[kc][0], src1);
            unsigned o1 = __shfl_sync(0xffffffffu, pf[kc][1], src1);
            unsigned e2 = __shfl_sync(0xffffffffu, pf[kc][2], src0);
            unsigned o2 = __shfl_sync(0xffffffffu, pf[kc][3], src0);
            unsigned e3 = __shfl_sync(0xffffffffu, pf[kc][2], src1);
            unsigned o3 = __shfl_sync(0xffffffffu, pf[kc][3], src1);
            unsigned af[4];
            af[0] = odd ? o0 : e0;   // (row g,   k=t)
            af[1] = odd ? o2 : e2;   // (row g+8, k=t)
            af[2] = odd ? o1 : e1;   // (row g,   k=t+4)
            af[3] = odd ? o3 : e3;   // (row g+8, k=t+4)
            int kb = kc << 3;
            #pragma unroll
            for (int n2 = 0; n2 < 16; n2++) {
                unsigned bb2[2];
                bb2[0] = Vs[(kb + t    ) * VSTR + (n2 << 3) + g];
                bb2[1] = Vs[(kb + t + 4) * VSTR + (n2 << 3) + g];
                mma_tf32(oacc[n2], af, bb2);
            }
        }
    }

    // ---- epilogue ----
    float il = 1.0f / l_lo;
    float ih = 1.0f / l_hi;
    float* obase = o + (size_t)b * SEQ * (NHQ * HD) + h * HD;
    int rlo = q0 + mrow + g;
    int rhi = rlo + 8;
    #pragma unroll
    for (int n2 = 0; n2 < 16; n2++) {
        int dn = (n2 << 3) + (t << 1);
        *(float2*)(obase + (size_t)rlo * (NHQ * HD) + dn) =
            make_float2(oacc[n2][0] * il, oacc[n2][1] * il);
        *(float2*)(obase + (size_t)rhi * (NHQ * HD) + dn) =
            make_float2(oacc[n2][2] * ih, oacc[n2][3] * ih);
    }
}

// ---------------------------------------------------------------------------
extern "C" void kernel_launch(void* const* d_in, const int* in_sizes, int n_in,
                              void* d_out, int out_size)
{
    const float* hidden = (const float*)d_in[0];
    const float* wq = (const float*)d_in[1];
    const float* wk = (const float*)d_in[2];
    const float* wv = (const float*)d_in[3];
    const float* wo = (const float*)d_in[4];
    const float* qw = (const float*)d_in[5];
    const float* kw = (const float*)d_in[6];
    float* out = (float*)d_out;

    float *q, *k, *v, *attn, *ct, *st;
    cudaGetSymbolAddress((void**)&q,    g_q);
    cudaGetSymbolAddress((void**)&k,    g_k);
    cudaGetSymbolAddress((void**)&v,    g_v);
    cudaGetSymbolAddress((void**)&attn, g_attn);
    cudaGetSymbolAddress((void**)&ct,   g_rope_cos);
    cudaGetSymbolAddress((void**)&st,   g_rope_sin);

    cudaFuncSetAttribute(flash_tf32, cudaFuncAttributeMaxDynamicSharedMemorySize,
                         FLASH_BYTES);

    rope_table<<<(SEQ*64 + 255) / 256, 256>>>(ct, st);
    gemm_tf32<<<dim3((NHQ*HD)/128,  MROWS/128), 256>>>(hidden, wq, q, MROWS, NHQ*HD,  HID);
    gemm_tf32<<<dim3((NHKV*HD)/128, MROWS/128), 256>>>(hidden, wk, k, MROWS, NHKV*HD, HID);
    gemm_tf32<<<dim3((NHKV*HD)/128, MROWS/128), 256>>>(hidden, wv, v, MROWS, NHKV*HD, HID);
    norm_rope<<<(MROWS*NHQ *32 + 255) / 256, 256>>>(q, qw, NHQ,  ct, st);
    norm_rope<<<(MROWS*NHKV*32 + 255) / 256, 256>>>(k, kw, NHKV, ct, st);
    flash_tf32<<<dim3(SEQ/FBQ, NHQ, NB), 256, FLASH_BYTES>>>(q, k, v, attn);
    gemm_tf32<<<dim3(HID/128, MROWS/128), 256>>>(attn, wo, out, MROWS, HID, NHQ*HD);
}

// round 7
// speedup vs baseline: 1.1540x; 1.0952x over previous
#include <cuda_runtime.h>
#include <cuda_bf16.h>
#include <math.h>

#define NB 2
#define SEQ 2048
#define HID 2048
#define NHQ 16
#define NHKV 8
#define HD 128
#define WIN 1024
#define MROWS (NB*SEQ)   // 4096

// ---------------- scratch (static device globals; no cudaMalloc allowed) ----
__device__ float g_q[(size_t)MROWS * NHQ * HD];
__device__ float g_k[(size_t)MROWS * NHKV * HD];
__device__ float g_v[(size_t)MROWS * NHKV * HD];
__device__ float g_attn[(size_t)MROWS * NHQ * HD];
__device__ float g_rope_cos[SEQ * 64];
__device__ float g_rope_sin[SEQ * 64];

// ---------------------------------------------------------------------------
__global__ void rope_table(float* __restrict__ ct, float* __restrict__ st)
{
    int idx = blockIdx.x * 256 + threadIdx.x;
    if (idx >= SEQ * 64) return;
    int pos = idx >> 6;
    int d   = idx & 63;
    double ang = (double)pos * pow(10000.0, -(double)d / 64.0);
    double s, c;
    sincos(ang, &s, &c);
    ct[idx] = (float)c;
    st[idx] = (float)s;
}

// ---------------------------------------------------------------------------
// helpers
// ---------------------------------------------------------------------------
__device__ __forceinline__ unsigned f2tf32(float x) {
    unsigned r;
    asm("cvt.rna.tf32.f32 %0, %1;" : "=r"(r) : "f"(x));
    return r;
}

__device__ __forceinline__ void mma_tf32(float c[4], const unsigned a[4],
                                         const unsigned b[2]) {
    asm volatile(
        "mma.sync.aligned.m16n8k8.row.col.f32.tf32.tf32.f32 "
        "{%0,%1,%2,%3}, {%4,%5,%6,%7}, {%8,%9}, {%0,%1,%2,%3};\n"
        : "+f"(c[0]), "+f"(c[1]), "+f"(c[2]), "+f"(c[3])
        : "r"(a[0]), "r"(a[1]), "r"(a[2]), "r"(a[3]), "r"(b[0]), "r"(b[1]));
}

__device__ __forceinline__ void mma_bf16(float c[4], const unsigned a[4],
                                         unsigned b0, unsigned b1) {
    asm volatile(
        "mma.sync.aligned.m16n8k16.row.col.f32.bf16.bf16.f32 "
        "{%0,%1,%2,%3}, {%4,%5,%6,%7}, {%8,%9}, {%0,%1,%2,%3};\n"
        : "+f"(c[0]), "+f"(c[1]), "+f"(c[2]), "+f"(c[3])
        : "r"(a[0]), "r"(a[1]), "r"(a[2]), "r"(a[3]), "r"(b0), "r"(b1));
}

__device__ __forceinline__ void ldsm4(unsigned r[4], unsigned addr) {
    asm volatile("ldmatrix.sync.aligned.m8n8.x4.shared.b16 {%0,%1,%2,%3}, [%4];"
        : "=r"(r[0]), "=r"(r[1]), "=r"(r[2]), "=r"(r[3]) : "r"(addr));
}

// pack two f32->bf16 (rn), low half = a, high half = b
__device__ __forceinline__ unsigned pack_bf16(float a, float b) {
    unsigned r;
    asm("cvt.rn.bf16x2.f32 %0, %2, %1;" : "=r"(r) : "f"(a), "f"(b));
    return r;
}
// truncation-hi split: hi = x with low 16 mantissa bits cleared
__device__ __forceinline__ float trunc_hi(float x) {
    return __uint_as_float(__float_as_uint(x) & 0xFFFF0000u);
}

// ---------------------------------------------------------------------------
// bf16 split-precision GEMM (NT): C[M,N] = A[M,K] @ W[N,K]^T  (f32 in/out)
//   C = Ahi@Bhi + Ahi@Blo + Alo@Bhi  (split computed in-kernel, fp32 accum)
// Block 128x128, BK=16, 256 thr, 8 warps (4M x 2N), warp tile 32x64.
// Smem tiles row-major [row][k16 bf16], row stride 48B (LDSM conflict-free).
// 2-stage double buffer, 1 syncthreads/iter, LDG prefetch overlaps mma.
// ---------------------------------------------------------------------------
#define RSTR 48                         // bytes per tile row
#define TILE_B (128 * RSTR)             // 6144 B per tile
#define STG_B  (4 * TILE_B)             // Ahi,Alo,Bhi,Blo = 24576
#define GEMM_SMEM (2 * STG_B)           // 49152

__global__ __launch_bounds__(256) void gemm_bf16s(
    const float* __restrict__ A, const float* __restrict__ Wt,
    float* __restrict__ C, int M, int N, int K)
{
    extern __shared__ __align__(16) char gsm[];
    unsigned sb;
    asm("{ .reg .u64 t; cvta.to.shared.u64 t, %1; cvt.u32.u64 %0, t; }"
        : "=r"(sb) : "l"(gsm));

    const int tid  = threadIdx.x;
    const int lane = tid & 31;
    const int warp = tid >> 5;
    const int wm = warp >> 1;           // 0..3
    const int wn = warp & 1;            // 0..1
    const int t  = lane & 3;
    const int m0 = blockIdx.y << 7;
    const int n0 = blockIdx.x << 7;

    // loader mapping: row = tid>>1 (0..127), half = tid&1 (k 8*half..)
    const int lrow = tid >> 1;
    const int lhal = tid & 1;
    const float* Ag = A  + (size_t)(m0 + lrow) * K + (lhal << 3);
    const float* Wg = Wt + (size_t)(n0 + lrow) * K + (lhal << 3);
    const unsigned sts_off = (unsigned)(lrow * RSTR + (lhal << 4));

    // LDSM lane addressing
    const int sub = lane >> 3;          // 0..3
    const int rin = lane & 7;
    // A: row = mr + (sub&1)*8 + rin, chunk = sub>>1
    const unsigned a_off = (unsigned)(((sub & 1) * 8 + rin) * RSTR + (sub >> 1) * 16);
    // B: row = nb + (sub>>1)*8 + rin, chunk = sub&1
    const unsigned b_off = (unsigned)(((sub >> 1) * 8 + rin) * RSTR + (sub & 1) * 16);

    float acc[2][8][4] = {};
    const int nIter = K >> 4;

    float4 ra0, ra1, rb0, rb1;
    ra0 = *(const float4*)(Ag);     ra1 = *(const float4*)(Ag + 4);
    rb0 = *(const float4*)(Wg);     rb1 = *(const float4*)(Wg + 4);

    for (int i = 0; i < nIter; i++) {
        unsigned stg = sb + (unsigned)(i & 1) * STG_B;
        // ---- split + store current regs ----
        {
            float a0h = trunc_hi(ra0.x), a1h = trunc_hi(ra0.y);
            float a2h = trunc_hi(ra0.z), a3h = trunc_hi(ra0.w);
            float a4h = trunc_hi(ra1.x), a5h = trunc_hi(ra1.y);
            float a6h = trunc_hi(ra1.z), a7h = trunc_hi(ra1.w);
            uint4 vh = make_uint4(
                __byte_perm(__float_as_uint(ra0.x), __float_as_uint(ra0.y), 0x7632),
                __byte_perm(__float_as_uint(ra0.z), __float_as_uint(ra0.w), 0x7632),
                __byte_perm(__float_as_uint(ra1.x), __float_as_uint(ra1.y), 0x7632),
                __byte_perm(__float_as_uint(ra1.z), __float_as_uint(ra1.w), 0x7632));
            uint4 vl = make_uint4(
                pack_bf16(ra0.x - a0h, ra0.y - a1h),
                pack_bf16(ra0.z - a2h, ra0.w - a3h),
                pack_bf16(ra1.x - a4h, ra1.y - a5h),
                pack_bf16(ra1.z - a6h, ra1.w - a7h));
            *(uint4*)(gsm + (stg - sb) + sts_off)          = vh;   // Ahi
            *(uint4*)(gsm + (stg - sb) + TILE_B + sts_off) = vl;   // Alo
            float b0h = trunc_hi(rb0.x), b1h = trunc_hi(rb0.y);
            float b2h = trunc_hi(rb0.z), b3h = trunc_hi(rb0.w);
            float b4h = trunc_hi(rb1.x), b5h = trunc_hi(rb1.y);
            float b6h = trunc_hi(rb1.z), b7h = trunc_hi(rb1.w);
            uint4 wh = make_uint4(
                __byte_perm(__float_as_uint(rb0.x), __float_as_uint(rb0.y), 0x7632),
                __byte_perm(__float_as_uint(rb0.z), __float_as_uint(rb0.w), 0x7632),
                __byte_perm(__float_as_uint(rb1.x), __float_as_uint(rb1.y), 0x7632),
                __byte_perm(__float_as_uint(rb1.z), __float_as_uint(rb1.w), 0x7632));
            uint4 wl = make_uint4(
                pack_bf16(rb0.x - b0h, rb0.y - b1h),
                pack_bf16(rb0.z - b2h, rb0.w - b3h),
                pack_bf16(rb1.x - b4h, rb1.y - b5h),
                pack_bf16(rb1.z - b6h, rb1.w - b7h));
            *(uint4*)(gsm + (stg - sb) + 2*TILE_B + sts_off) = wh; // Bhi
            *(uint4*)(gsm + (stg - sb) + 3*TILE_B + sts_off) = wl; // Blo
        }
        // ---- prefetch next k-block ----
        if (i + 1 < nIter) {
            int k0 = (i + 1) << 4;
            ra0 = *(const float4*)(Ag + k0);  ra1 = *(const float4*)(Ag + k0 + 4);
            rb0 = *(const float4*)(Wg + k0);  rb1 = *(const float4*)(Wg + k0 + 4);
        }
        __syncthreads();

        // ---- fragments + mma: 3 terms ----
        unsigned Ahi_b = stg + (unsigned)((wm << 5) * RSTR);
        unsigned Alo_b = Ahi_b + TILE_B;
        unsigned Bhi_b = stg + 2*TILE_B + (unsigned)((wn << 6) * RSTR);
        unsigned Blo_b = Bhi_b + TILE_B;

        unsigned ah[2][4], bh[4][4];
        #pragma unroll
        for (int mi = 0; mi < 2; mi++)
            ldsm4(ah[mi], Ahi_b + (unsigned)((mi << 4) * RSTR) + a_off);
        #pragma unroll
        for (int p = 0; p < 4; p++)
            ldsm4(bh[p], Bhi_b + (unsigned)((p << 4) * RSTR) + b_off);
        // term 1: Ahi * Bhi
        #pragma unroll
        for (int mi = 0; mi < 2; mi++)
            #pragma unroll
            for (int p = 0; p < 4; p++) {
                mma_bf16(acc[mi][(p<<1)  ], ah[mi], bh[p][0], bh[p][1]);
                mma_bf16(acc[mi][(p<<1)+1], ah[mi], bh[p][2], bh[p][3]);
            }
        // term 2: Alo * Bhi (reuse bh)
        unsigned al[2][4];
        #pragma unroll
        for (int mi = 0; mi < 2; mi++)
            ldsm4(al[mi], Alo_b + (unsigned)((mi << 4) * RSTR) + a_off);
        #pragma unroll
        for (int mi = 0; mi < 2; mi++)
            #pragma unroll
            for (int p = 0; p < 4; p++) {
                mma_bf16(acc[mi][(p<<1)  ], al[mi], bh[p][0], bh[p][1]);
                mma_bf16(acc[mi][(p<<1)+1], al[mi], bh[p][2], bh[p][3]);
            }
        // term 3: Ahi * Blo
        unsigned bl[4][4];
        #pragma unroll
        for (int p = 0; p < 4; p++)
            ldsm4(bl[p], Blo_b + (unsigned)((p << 4) * RSTR) + b_off);
        #pragma unroll
        for (int mi = 0; mi < 2; mi++)
            #pragma unroll
            for (int p = 0; p < 4; p++) {
                mma_bf16(acc[mi][(p<<1)  ], ah[mi], bl[p][0], bl[p][1]);
                mma_bf16(acc[mi][(p<<1)+1], ah[mi], bl[p][2], bl[p][3]);
            }
    }

    // ---- epilogue (same validated layout as R2) ----
    const int gid = lane >> 2;
    #pragma unroll
    for (int mi = 0; mi < 2; mi++) {
        int r0 = m0 + (wm << 5) + (mi << 4) + gid;
        #pragma unroll
        for (int ni = 0; ni < 8; ni++) {
            int cc = n0 + (wn << 6) + (ni << 3) + (t << 1);
            *(float2*)(C + (size_t)r0 * N + cc) =
                make_float2(acc[mi][ni][0], acc[mi][ni][1]);
            *(float2*)(C + (size_t)(r0 + 8) * N + cc) =
                make_float2(acc[mi][ni][2], acc[mi][ni][3]);
        }
    }
}

// ---------------------------------------------------------------------------
// RMSNorm + RoPE via table (unchanged)
// ---------------------------------------------------------------------------
__global__ __launch_bounds__(256) void norm_rope(
    float* __restrict__ x, const float* __restrict__ w, int n_heads,
    const float* __restrict__ ct, const float* __restrict__ st)
{
    int gw   = (blockIdx.x * 256 + threadIdx.x) >> 5;
    int lane = threadIdx.x & 31;
    if (gw >= MROWS * n_heads) return;
    int m = gw / n_heads;
    int h = gw - m * n_heads;
    int pos = m & (SEQ - 1);
    float* row = x + (size_t)m * (n_heads * HD) + h * HD;
    float x0 = row[lane], x1 = row[lane+32], x2 = row[lane+64], x3 = row[lane+96];
    float ss = x0*x0 + x1*x1 + x2*x2 + x3*x3;
    #pragma unroll
    for (int o = 16; o; o >>= 1) ss += __shfl_xor_sync(0xffffffffu, ss, o);
    float rstd = rsqrtf(ss * (1.0f / HD) + 1e-6f);
    float y0 = x0 * rstd * (1.f + w[lane]);
    float y1 = x1 * rstd * (1.f + w[lane+32]);
    float y2 = x2 * rstd * (1.f + w[lane+64]);
    float y3 = x3 * rstd * (1.f + w[lane+96]);
    float c0 = ct[pos*64 + lane],      s0 = st[pos*64 + lane];
    float c1 = ct[pos*64 + lane + 32], s1 = st[pos*64 + lane + 32];
    row[lane]      = y0 * c0 - y2 * s0;
    row[lane+64]   = y2 * c0 + y0 * s0;
    row[lane+32]   = y1 * c1 - y3 * s1;
    row[lane+96]   = y3 * c1 + y1 * s1;
}

// ---------------------------------------------------------------------------
// Flash attention (R5 passing version, unchanged): BQ=128, register softmax.
// ---------------------------------------------------------------------------
#define FBQ 128
#define FBK 64
#define QSTR 132
#define KSTR 72
#define VSTR 136
#define FLASH_WORDS (128*QSTR + 128*KSTR + 64*VSTR)
#define FLASH_BYTES (FLASH_WORDS * 4)

__global__ __launch_bounds__(256) void flash_tf32(
    const float* __restrict__ q, const float* __restrict__ k,
    const float* __restrict__ v, float* __restrict__ o)
{
    extern __shared__ unsigned smu[];
    unsigned* Qs  = smu;
    unsigned* KsT = Qs + 128 * QSTR;
    unsigned* Vs  = KsT + 128 * KSTR;

    const int tid  = threadIdx.x;
    const int lane = tid & 31;
    const int warp = tid >> 5;
    const int g    = lane >> 2;
    const int t    = lane & 3;
    const int mrow = warp << 4;

    const int q0 = blockIdx.x * FBQ;
    const int h  = blockIdx.y;
    const int b  = blockIdx.z;
    const int hk = h >> 1;
    const float* qbase = q + (size_t)b * SEQ * (NHQ  * HD) + h  * HD;
    const float* kbase = k + (size_t)b * SEQ * (NHKV * HD) + hk * HD;
    const float* vbase = v + (size_t)b * SEQ * (NHKV * HD) + hk * HD;
    const float scale = 0.08838834764831845f;

    #pragma unroll
    for (int rep = 0; rep < 16; rep++) {
        int idx = rep * 256 + tid;
        int r   = idx >> 5;
        int dc  = (idx & 31) << 2;
        float4 va = *(const float4*)(qbase + (size_t)(q0 + r) * (NHQ * HD) + dc);
        unsigned* dst = Qs + r * QSTR + dc;
        dst[0] = f2tf32(va.x * scale); dst[1] = f2tf32(va.y * scale);
        dst[2] = f2tf32(va.z * scale); dst[3] = f2tf32(va.w * scale);
    }

    float oacc[16][4] = {};
    float m_lo = -1e30f, m_hi = -1e30f, l_lo = 0.f, l_hi = 0.f;
    const int qi_lo = q0 + mrow + g;
    const int qi_hi = qi_lo + 8;

    int jlo = q0 - (WIN - 1); if (jlo < 0) jlo = 0;
    const int jstart = jlo & ~(FBK - 1);

    const int src0 = (lane & ~3) | (t >> 1);
    const int src1 = src0 + 2;
    const bool odd = t & 1;

    for (int j0 = jstart; j0 < q0 + FBQ; j0 += FBK) {
        __syncthreads();
        {
            int r  = tid >> 2;
            int c4 = (tid & 3) << 2;
            #pragma unroll
            for (int sub2 = 0; sub2 < 8; sub2++) {
                float4 kv = *(const float4*)(kbase + (size_t)(j0 + r) * (NHKV * HD) + sub2 * 16 + c4);
                int dbase = sub2 * 16 + c4;
                KsT[(dbase+0)*KSTR + r] = f2tf32(kv.x);
                KsT[(dbase+1)*KSTR + r] = f2tf32(kv.y);
                KsT[(dbase+2)*KSTR + r] = f2tf32(kv.z);
                KsT[(dbase+3)*KSTR + r] = f2tf32(kv.w);
            }
        }
        #pragma unroll
        for (int rep = 0; rep < 8; rep++) {
            int idx = rep * 256 + tid;
            int r   = idx >> 5;
            int dc  = (idx & 31) << 2;
            float4 vv = *(const float4*)(vbase + (size_t)(j0 + r) * (NHKV * HD) + dc);
            unsigned* dst = Vs + r * VSTR + dc;
            dst[0] = f2tf32(vv.x); dst[1] = f2tf32(vv.y);
            dst[2] = f2tf32(vv.z); dst[3] = f2tf32(vv.w);
        }
        __syncthreads();

        float sacc[8][4] = {};
        #pragma unroll
        for (int kc = 0; kc < 16; kc++) {
            int kb = kc << 3;
            unsigned qa[4];
            qa[0] = Qs[(mrow + g    ) * QSTR + kb + t];
            qa[1] = Qs[(mrow + g + 8) * QSTR + kb + t];
            qa[2] = Qs[(mrow + g    ) * QSTR + kb + t + 4];
            qa[3] = Qs[(mrow + g + 8) * QSTR + kb + t + 4];
            unsigned bb[8][2];
            #pragma unroll
            for (int ni = 0; ni < 8; ni++) {
                bb[ni][0] = KsT[(kb + t    ) * KSTR + (ni << 3) + g];
                bb[ni][1] = KsT[(kb + t + 4) * KSTR + (ni << 3) + g];
            }
            #pragma unroll
            for (int ni = 0; ni < 8; ni++)
                mma_tf32(sacc[ni], qa, bb[ni]);
        }

        float mx_lo = -1e30f, mx_hi = -1e30f;
        #pragma unroll
        for (int ni = 0; ni < 8; ni++) {
            int c0 = j0 + (ni << 3) + (t << 1);
            int c1 = c0 + 1;
            if (!((c0 <= qi_lo) && (c0 > qi_lo - WIN))) sacc[ni][0] = -1e30f;
            if (!((c1 <= qi_lo) && (c1 > qi_lo - WIN))) sacc[ni][1] = -1e30f;
            if (!((c0 <= qi_hi) && (c0 > qi_hi - WIN))) sacc[ni][2] = -1e30f;
            if (!((c1 <= qi_hi) && (c1 > qi_hi - WIN))) sacc[ni][3] = -1e30f;
            mx_lo = fmaxf(mx_lo, fmaxf(sacc[ni][0], sacc[ni][1]));
            mx_hi = fmaxf(mx_hi, fmaxf(sacc[ni][2], sacc[ni][3]));
        }
        mx_lo = fmaxf(mx_lo, __shfl_xor_sync(0xffffffffu, mx_lo, 1));
        mx_lo = fmaxf(mx_lo, __shfl_xor_sync(0xffffffffu, mx_lo, 2));
        mx_hi = fmaxf(mx_hi, __shfl_xor_sync(0xffffffffu, mx_hi, 1));
        mx_hi = fmaxf(mx_hi, __shfl_xor_sync(0xffffffffu, mx_hi, 2));

        float mnl = fmaxf(m_lo, mx_lo);
        float mnh = fmaxf(m_hi, mx_hi);
        float cl  = __expf(m_lo - mnl);
        float ch  = __expf(m_hi - mnh);
        m_lo = mnl; m_hi = mnh;

        float ps_lo = 0.f, ps_hi = 0.f;
        unsigned pf[8][4];
        #pragma unroll
        for (int ni = 0; ni < 8; ni++) {
            float p0 = (sacc[ni][0] > -1e29f) ? __expf(sacc[ni][0] - mnl) : 0.f;
            float p1 = (sacc[ni][1] > -1e29f) ? __expf(sacc[ni][1] - mnl) : 0.f;
            float p2 = (sacc[ni][2] > -1e29f) ? __expf(sacc[ni][2] - mnh) : 0.f;
            float p3 = (sacc[ni][3] > -1e29f) ? __expf(sacc[ni][3] - mnh) : 0.f;
            ps_lo += p0 + p1;
            ps_hi += p2 + p3;
            pf[ni][0] = f2tf32(p0); pf[ni][1] = f2tf32(p1);
            pf[ni][2] = f2tf32(p2); pf[ni][3] = f2tf32(p3);
        }
        ps_lo += __shfl_xor_sync(0xffffffffu, ps_lo, 1);
        ps_lo += __shfl_xor_sync(0xffffffffu, ps_lo, 2);
        ps_hi += __shfl_xor_sync(0xffffffffu, ps_hi, 1);
        ps_hi += __shfl_xor_sync(0xffffffffu, ps_hi, 2);
        l_lo = l_lo * cl + ps_lo;
        l_hi = l_hi * ch + ps_hi;

        #pragma unroll
        for (int n2 = 0; n2 < 16; n2++) {
            oacc[n2][0] *= cl; oacc[n2][1] *= cl;
            oacc[n2][2] *= ch; oacc[n2][3] *= ch;
        }

        #pragma unroll
        for (int kc = 0; kc < 8; kc++) {
            unsigned e0 = __shfl_sync(0xffffffffu, pf[kc][0], src0);
            unsigned o0 = __shfl_sync(0xffffffffu, pf[kc][1], src0);
            unsigned e1 = __shfl_sync(0xffffffffu, pf[kc][0], src1);
            unsigned o1 = __shfl_sync(0xffffffffu, pf[kc][1], src1);
            unsigned e2 = __shfl_sync(0xffffffffu, pf[kc][2], src0);
            unsigned o2 = __shfl_sync(0xffffffffu, pf[kc][3], src0);
            unsigned e3 = __shfl_sync(0xffffffffu, pf[kc][2], src1);
            unsigned o3 = __shfl_sync(0xffffffffu, pf[kc][3], src1);
            unsigned af[4];
            af[0] = odd ? o0 : e0;
            af[1] = odd ? o2 : e2;
            af[2] = odd ? o1 : e1;
            af[3] = odd ? o3 : e3;
            int kb = kc << 3;
            #pragma unroll
            for (int n2 = 0; n2 < 16; n2++) {
                unsigned bb2[2];
                bb2[0] = Vs[(kb + t    ) * VSTR + (n2 << 3) + g];
                bb2[1] = Vs[(kb + t + 4) * VSTR + (n2 << 3) + g];
                mma_tf32(oacc[n2], af, bb2);
            }
        }
    }

    float il = 1.0f / l_lo;
    float ih = 1.0f / l_hi;
    float* obase = o + (size_t)b * SEQ * (NHQ * HD) + h * HD;
    int rlo = q0 + mrow + g;
    int rhi = rlo + 8;
    #pragma unroll
    for (int n2 = 0; n2 < 16; n2++) {
        int dn = (n2 << 3) + (t << 1);
        *(float2*)(obase + (size_t)rlo * (NHQ * HD) + dn) =
            make_float2(oacc[n2][0] * il, oacc[n2][1] * il);
        *(float2*)(obase + (size_t)rhi * (NHQ * HD) + dn) =
            make_float2(oacc[n2][2] * ih, oacc[n2][3] * ih);
    }
}

// ---------------------------------------------------------------------------
extern "C" void kernel_launch(void* const* d_in, const int* in_sizes, int n_in,
                              void* d_out, int out_size)
{
    const float* hidden = (const float*)d_in[0];
    const float* wq = (const float*)d_in[1];
    const float* wk = (const float*)d_in[2];
    const float* wv = (const float*)d_in[3];
    const float* wo = (const float*)d_in[4];
    const float* qw = (const float*)d_in[5];
    const float* kw = (const float*)d_in[6];
    float* out = (float*)d_out;

    float *q, *k, *v, *attn, *ct, *st;
    cudaGetSymbolAddress((void**)&q,    g_q);
    cudaGetSymbolAddress((void**)&k,    g_k);
    cudaGetSymbolAddress((void**)&v,    g_v);
    cudaGetSymbolAddress((void**)&attn, g_attn);
    cudaGetSymbolAddress((void**)&ct,   g_rope_cos);
    cudaGetSymbolAddress((void**)&st,   g_rope_sin);

    cudaFuncSetAttribute(flash_tf32, cudaFuncAttributeMaxDynamicSharedMemorySize,
                         FLASH_BYTES);
    cudaFuncSetAttribute(gemm_bf16s, cudaFuncAttributeMaxDynamicSharedMemorySize,
                         GEMM_SMEM);

    rope_table<<<(SEQ*64 + 255) / 256, 256>>>(ct, st);
    gemm_bf16s<<<dim3((NHQ*HD)/128,  MROWS/128), 256, GEMM_SMEM>>>(hidden, wq, q, MROWS, NHQ*HD,  HID);
    gemm_bf16s<<<dim3((NHKV*HD)/128, MROWS/128), 256, GEMM_SMEM>>>(hidden, wk, k, MROWS, NHKV*HD, HID);
    gemm_bf16s<<<dim3((NHKV*HD)/128, MROWS/128), 256, GEMM_SMEM>>>(hidden, wv, v, MROWS, NHKV*HD, HID);
    norm_rope<<<(MROWS*NHQ *32 + 255) / 256, 256>>>(q, qw, NHQ,  ct, st);
    norm_rope<<<(MROWS*NHKV*32 + 255) / 256, 256>>>(k, kw, NHKV, ct, st);
    flash_tf32<<<dim3(SEQ/FBQ, NHQ, NB), 256, FLASH_BYTES>>>(q, k, v, attn);
    gemm_bf16s<<<dim3(HID/128, MROWS/128), 256, GEMM_SMEM>>>(attn, wo, out, MROWS, HID, NHQ*HD);
}

// round 8
// speedup vs baseline: 1.2785x; 1.1079x over previous
#include <cuda_runtime.h>
#include <cuda_bf16.h>
#include <math.h>

#define NB 2
#define SEQ 2048
#define HID 2048
#define NHQ 16
#define NHKV 8
#define HD 128
#define WIN 1024
#define MROWS (NB*SEQ)   // 4096

// ---------------- scratch (static device globals; no cudaMalloc allowed) ----
__device__ float g_q[(size_t)MROWS * NHQ * HD];
__device__ float g_k[(size_t)MROWS * NHKV * HD];
__device__ float g_v[(size_t)MROWS * NHKV * HD];
__device__ float g_attn[(size_t)MROWS * NHQ * HD];
__device__ float g_rope_cos[SEQ * 64];
__device__ float g_rope_sin[SEQ * 64];

// ---------------------------------------------------------------------------
__global__ void rope_table(float* __restrict__ ct, float* __restrict__ st)
{
    int idx = blockIdx.x * 256 + threadIdx.x;
    if (idx >= SEQ * 64) return;
    int pos = idx >> 6;
    int d   = idx & 63;
    double ang = (double)pos * pow(10000.0, -(double)d / 64.0);
    double s, c;
    sincos(ang, &s, &c);
    ct[idx] = (float)c;
    st[idx] = (float)s;
}

// ---------------------------------------------------------------------------
// helpers
// ---------------------------------------------------------------------------
__device__ __forceinline__ unsigned f2tf32(float x) {
    unsigned r;
    asm("cvt.rna.tf32.f32 %0, %1;" : "=r"(r) : "f"(x));
    return r;
}

__device__ __forceinline__ void mma_tf32(float c[4], const unsigned a[4],
                                         const unsigned b[2]) {
    asm volatile(
        "mma.sync.aligned.m16n8k8.row.col.f32.tf32.tf32.f32 "
        "{%0,%1,%2,%3}, {%4,%5,%6,%7}, {%8,%9}, {%0,%1,%2,%3};\n"
        : "+f"(c[0]), "+f"(c[1]), "+f"(c[2]), "+f"(c[3])
        : "r"(a[0]), "r"(a[1]), "r"(a[2]), "r"(a[3]), "r"(b[0]), "r"(b[1]));
}

__device__ __forceinline__ void mma_bf16(float c[4], const unsigned a[4],
                                         unsigned b0, unsigned b1) {
    asm volatile(
        "mma.sync.aligned.m16n8k16.row.col.f32.bf16.bf16.f32 "
        "{%0,%1,%2,%3}, {%4,%5,%6,%7}, {%8,%9}, {%0,%1,%2,%3};\n"
        : "+f"(c[0]), "+f"(c[1]), "+f"(c[2]), "+f"(c[3])
        : "r"(a[0]), "r"(a[1]), "r"(a[2]), "r"(a[3]), "r"(b0), "r"(b1));
}

__device__ __forceinline__ void ldsm4(unsigned r[4], unsigned addr) {
    asm volatile("ldmatrix.sync.aligned.m8n8.x4.shared.b16 {%0,%1,%2,%3}, [%4];"
        : "=r"(r[0]), "=r"(r[1]), "=r"(r[2]), "=r"(r[3]) : "r"(addr));
}

__device__ __forceinline__ unsigned pack_bf16(float a, float b) {
    unsigned r;
    asm("cvt.rn.bf16x2.f32 %0, %2, %1;" : "=r"(r) : "f"(a), "f"(b));
    return r;
}
__device__ __forceinline__ float trunc_hi(float x) {
    return __uint_as_float(__float_as_uint(x) & 0xFFFF0000u);
}

// ---------------------------------------------------------------------------
// bf16 split-precision GEMM core (validated R7). Used by both the fused QKV
// kernel and the O-projection kernel.
// ---------------------------------------------------------------------------
#define RSTR 48
#define TILE_B (128 * RSTR)
#define STG_B  (4 * TILE_B)
#define GEMM_SMEM (2 * STG_B)   // 49152

__device__ __forceinline__ void gemm_core(
    const float* __restrict__ A, const float* __restrict__ Wt,
    float* __restrict__ C, int m0, int n0, int N, int K, char* gsm)
{
    unsigned sb;
    asm("{ .reg .u64 t; cvta.to.shared.u64 t, %1; cvt.u32.u64 %0, t; }"
        : "=r"(sb) : "l"(gsm));

    const int tid  = threadIdx.x;
    const int lane = tid & 31;
    const int warp = tid >> 5;
    const int wm = warp >> 1;
    const int wn = warp & 1;
    const int t  = lane & 3;

    const int lrow = tid >> 1;
    const int lhal = tid & 1;
    const float* Ag = A  + (size_t)(m0 + lrow) * K + (lhal << 3);
    const float* Wg = Wt + (size_t)(n0 + lrow) * K + (lhal << 3);
    const unsigned sts_off = (unsigned)(lrow * RSTR + (lhal << 4));

    const int sub = lane >> 3;
    const int rin = lane & 7;
    const unsigned a_off = (unsigned)(((sub & 1) * 8 + rin) * RSTR + (sub >> 1) * 16);
    const unsigned b_off = (unsigned)(((sub >> 1) * 8 + rin) * RSTR + (sub & 1) * 16);

    float acc[2][8][4] = {};
    const int nIter = K >> 4;

    float4 ra0, ra1, rb0, rb1;
    ra0 = *(const float4*)(Ag);     ra1 = *(const float4*)(Ag + 4);
    rb0 = *(const float4*)(Wg);     rb1 = *(const float4*)(Wg + 4);

    for (int i = 0; i < nIter; i++) {
        unsigned stgo = (unsigned)(i & 1) * STG_B;
        {
            float a0h = trunc_hi(ra0.x), a1h = trunc_hi(ra0.y);
            float a2h = trunc_hi(ra0.z), a3h = trunc_hi(ra0.w);
            float a4h = trunc_hi(ra1.x), a5h = trunc_hi(ra1.y);
            float a6h = trunc_hi(ra1.z), a7h = trunc_hi(ra1.w);
            uint4 vh = make_uint4(
                __byte_perm(__float_as_uint(ra0.x), __float_as_uint(ra0.y), 0x7632),
                __byte_perm(__float_as_uint(ra0.z), __float_as_uint(ra0.w), 0x7632),
                __byte_perm(__float_as_uint(ra1.x), __float_as_uint(ra1.y), 0x7632),
                __byte_perm(__float_as_uint(ra1.z), __float_as_uint(ra1.w), 0x7632));
            uint4 vl = make_uint4(
                pack_bf16(ra0.x - a0h, ra0.y - a1h),
                pack_bf16(ra0.z - a2h, ra0.w - a3h),
                pack_bf16(ra1.x - a4h, ra1.y - a5h),
                pack_bf16(ra1.z - a6h, ra1.w - a7h));
            *(uint4*)(gsm + stgo + sts_off)          = vh;
            *(uint4*)(gsm + stgo + TILE_B + sts_off) = vl;
            float b0h = trunc_hi(rb0.x), b1h = trunc_hi(rb0.y);
            float b2h = trunc_hi(rb0.z), b3h = trunc_hi(rb0.w);
            float b4h = trunc_hi(rb1.x), b5h = trunc_hi(rb1.y);
            float b6h = trunc_hi(rb1.z), b7h = trunc_hi(rb1.w);
            uint4 wh = make_uint4(
                __byte_perm(__float_as_uint(rb0.x), __float_as_uint(rb0.y), 0x7632),
                __byte_perm(__float_as_uint(rb0.z), __float_as_uint(rb0.w), 0x7632),
                __byte_perm(__float_as_uint(rb1.x), __float_as_uint(rb1.y), 0x7632),
                __byte_perm(__float_as_uint(rb1.z), __float_as_uint(rb1.w), 0x7632));
            uint4 wl = make_uint4(
                pack_bf16(rb0.x - b0h, rb0.y - b1h),
                pack_bf16(rb0.z - b2h, rb0.w - b3h),
                pack_bf16(rb1.x - b4h, rb1.y - b5h),
                pack_bf16(rb1.z - b6h, rb1.w - b7h));
            *(uint4*)(gsm + stgo + 2*TILE_B + sts_off) = wh;
            *(uint4*)(gsm + stgo + 3*TILE_B + sts_off) = wl;
        }
        if (i + 1 < nIter) {
            int k0 = (i + 1) << 4;
            ra0 = *(const float4*)(Ag + k0);  ra1 = *(const float4*)(Ag + k0 + 4);
            rb0 = *(const float4*)(Wg + k0);  rb1 = *(const float4*)(Wg + k0 + 4);
        }
        __syncthreads();

        unsigned stg = sb + stgo;
        unsigned Ahi_b = stg + (unsigned)((wm << 5) * RSTR);
        unsigned Alo_b = Ahi_b + TILE_B;
        unsigned Bhi_b = stg + 2*TILE_B + (unsigned)((wn << 6) * RSTR);
        unsigned Blo_b = Bhi_b + TILE_B;

        unsigned ah[2][4], bh[4][4];
        #pragma unroll
        for (int mi = 0; mi < 2; mi++)
            ldsm4(ah[mi], Ahi_b + (unsigned)((mi << 4) * RSTR) + a_off);
        #pragma unroll
        for (int p = 0; p < 4; p++)
            ldsm4(bh[p], Bhi_b + (unsigned)((p << 4) * RSTR) + b_off);
        #pragma unroll
        for (int mi = 0; mi < 2; mi++)
            #pragma unroll
            for (int p = 0; p < 4; p++) {
                mma_bf16(acc[mi][(p<<1)  ], ah[mi], bh[p][0], bh[p][1]);
                mma_bf16(acc[mi][(p<<1)+1], ah[mi], bh[p][2], bh[p][3]);
            }
        unsigned al[2][4];
        #pragma unroll
        for (int mi = 0; mi < 2; mi++)
            ldsm4(al[mi], Alo_b + (unsigned)((mi << 4) * RSTR) + a_off);
        #pragma unroll
        for (int mi = 0; mi < 2; mi++)
            #pragma unroll
            for (int p = 0; p < 4; p++) {
                mma_bf16(acc[mi][(p<<1)  ], al[mi], bh[p][0], bh[p][1]);
                mma_bf16(acc[mi][(p<<1)+1], al[mi], bh[p][2], bh[p][3]);
            }
        unsigned bl[4][4];
        #pragma unroll
        for (int p = 0; p < 4; p++)
            ldsm4(bl[p], Blo_b + (unsigned)((p << 4) * RSTR) + b_off);
        #pragma unroll
        for (int mi = 0; mi < 2; mi++)
            #pragma unroll
            for (int p = 0; p < 4; p++) {
                mma_bf16(acc[mi][(p<<1)  ], ah[mi], bl[p][0], bl[p][1]);
                mma_bf16(acc[mi][(p<<1)+1], ah[mi], bl[p][2], bl[p][3]);
            }
    }

    const int gid = lane >> 2;
    #pragma unroll
    for (int mi = 0; mi < 2; mi++) {
        int r0 = m0 + (wm << 5) + (mi << 4) + gid;
        #pragma unroll
        for (int ni = 0; ni < 8; ni++) {
            int cc = n0 + (wn << 6) + (ni << 3) + (t << 1);
            *(float2*)(C + (size_t)r0 * N + cc) =
                make_float2(acc[mi][ni][0], acc[mi][ni][1]);
            *(float2*)(C + (size_t)(r0 + 8) * N + cc) =
                make_float2(acc[mi][ni][2], acc[mi][ni][3]);
        }
    }
}

// Fused QKV: grid (32 n-blocks, 32 m-blocks). n 0-15 -> Q, 16-23 -> K, 24-31 -> V.
__global__ __launch_bounds__(256) void gemm_qkv(
    const float* __restrict__ A,
    const float* __restrict__ wq, const float* __restrict__ wk,
    const float* __restrict__ wv,
    float* __restrict__ q, float* __restrict__ k, float* __restrict__ v)
{
    extern __shared__ __align__(16) char gsm[];
    int nb = blockIdx.x;
    int m0 = blockIdx.y << 7;
    const float* Wt; float* C; int N; int n0;
    if (nb < 16)      { Wt = wq; C = q; N = NHQ*HD;  n0 = nb << 7; }
    else if (nb < 24) { Wt = wk; C = k; N = NHKV*HD; n0 = (nb - 16) << 7; }
    else              { Wt = wv; C = v; N = NHKV*HD; n0 = (nb - 24) << 7; }
    gemm_core(A, Wt, C, m0, n0, N, HID, gsm);
}

// O projection
__global__ __launch_bounds__(256) void gemm_o(
    const float* __restrict__ A, const float* __restrict__ Wt,
    float* __restrict__ C)
{
    extern __shared__ __align__(16) char gsm[];
    gemm_core(A, Wt, C, blockIdx.y << 7, blockIdx.x << 7, HID, NHQ*HD, gsm);
}

// ---------------------------------------------------------------------------
// Fused RMSNorm + RoPE for BOTH q and k in one launch.
// ---------------------------------------------------------------------------
__global__ __launch_bounds__(256) void norm_rope_both(
    float* __restrict__ xq, const float* __restrict__ wq,
    float* __restrict__ xk, const float* __restrict__ wk,
    const float* __restrict__ ct, const float* __restrict__ st)
{
    int gw   = (blockIdx.x * 256 + threadIdx.x) >> 5;
    int lane = threadIdx.x & 31;
    float* x; const float* w; int n_heads;
    if (gw < MROWS * NHQ) { x = xq; w = wq; n_heads = NHQ; }
    else { gw -= MROWS * NHQ; if (gw >= MROWS * NHKV) return;
           x = xk; w = wk; n_heads = NHKV; }
    int m = gw / n_heads;
    int h = gw - m * n_heads;
    int pos = m & (SEQ - 1);
    float* row = x + (size_t)m * (n_heads * HD) + h * HD;
    float x0 = row[lane], x1 = row[lane+32], x2 = row[lane+64], x3 = row[lane+96];
    float ss = x0*x0 + x1*x1 + x2*x2 + x3*x3;
    #pragma unroll
    for (int o = 16; o; o >>= 1) ss += __shfl_xor_sync(0xffffffffu, ss, o);
    float rstd = rsqrtf(ss * (1.0f / HD) + 1e-6f);
    float y0 = x0 * rstd * (1.f + w[lane]);
    float y1 = x1 * rstd * (1.f + w[lane+32]);
    float y2 = x2 * rstd * (1.f + w[lane+64]);
    float y3 = x3 * rstd * (1.f + w[lane+96]);
    float c0 = ct[pos*64 + lane],      s0 = st[pos*64 + lane];
    float c1 = ct[pos*64 + lane + 32], s1 = st[pos*64 + lane + 32];
    row[lane]      = y0 * c0 - y2 * s0;
    row[lane+64]   = y2 * c0 + y0 * s0;
    row[lane+32]   = y1 * c1 - y3 * s1;
    row[lane+96]   = y3 * c1 + y1 * s1;
}

// ---------------------------------------------------------------------------
// Flash attention (R7 passing version, unchanged): BQ=128, register softmax.
// ---------------------------------------------------------------------------
#define FBQ 128
#define FBK 64
#define QSTR 132
#define KSTR 72
#define VSTR 136
#define FLASH_WORDS (128*QSTR + 128*KSTR + 64*VSTR)
#define FLASH_BYTES (FLASH_WORDS * 4)

__global__ __launch_bounds__(256) void flash_tf32(
    const float* __restrict__ q, const float* __restrict__ k,
    const float* __restrict__ v, float* __restrict__ o)
{
    extern __shared__ unsigned smu[];
    unsigned* Qs  = smu;
    unsigned* KsT = Qs + 128 * QSTR;
    unsigned* Vs  = KsT + 128 * KSTR;

    const int tid  = threadIdx.x;
    const int lane = tid & 31;
    const int warp = tid >> 5;
    const int g    = lane >> 2;
    const int t    = lane & 3;
    const int mrow = warp << 4;

    const int q0 = blockIdx.x * FBQ;
    const int h  = blockIdx.y;
    const int b  = blockIdx.z;
    const int hk = h >> 1;
    const float* qbase = q + (size_t)b * SEQ * (NHQ  * HD) + h  * HD;
    const float* kbase = k + (size_t)b * SEQ * (NHKV * HD) + hk * HD;
    const float* vbase = v + (size_t)b * SEQ * (NHKV * HD) + hk * HD;
    const float scale = 0.08838834764831845f;

    #pragma unroll
    for (int rep = 0; rep < 16; rep++) {
        int idx = rep * 256 + tid;
        int r   = idx >> 5;
        int dc  = (idx & 31) << 2;
        float4 va = *(const float4*)(qbase + (size_t)(q0 + r) * (NHQ * HD) + dc);
        unsigned* dst = Qs + r * QSTR + dc;
        dst[0] = f2tf32(va.x * scale); dst[1] = f2tf32(va.y * scale);
        dst[2] = f2tf32(va.z * scale); dst[3] = f2tf32(va.w * scale);
    }

    float oacc[16][4] = {};
    float m_lo = -1e30f, m_hi = -1e30f, l_lo = 0.f, l_hi = 0.f;
    const int qi_lo = q0 + mrow + g;
    const int qi_hi = qi_lo + 8;

    int jlo = q0 - (WIN - 1); if (jlo < 0) jlo = 0;
    const int jstart = jlo & ~(FBK - 1);

    const int src0 = (lane & ~3) | (t >> 1);
    const int src1 = src0 + 2;
    const bool odd = t & 1;

    for (int j0 = jstart; j0 < q0 + FBQ; j0 += FBK) {
        __syncthreads();
        {
            int r  = tid >> 2;
            int c4 = (tid & 3) << 2;
            #pragma unroll
            for (int sub2 = 0; sub2 < 8; sub2++) {
                float4 kv = *(const float4*)(kbase + (size_t)(j0 + r) * (NHKV * HD) + sub2 * 16 + c4);
                int dbase = sub2 * 16 + c4;
                KsT[(dbase+0)*KSTR + r] = f2tf32(kv.x);
                KsT[(dbase+1)*KSTR + r] = f2tf32(kv.y);
                KsT[(dbase+2)*KSTR + r] = f2tf32(kv.z);
                KsT[(dbase+3)*KSTR + r] = f2tf32(kv.w);
            }
        }
        #pragma unroll
        for (int rep = 0; rep < 8; rep++) {
            int idx = rep * 256 + tid;
            int r   = idx >> 5;
            int dc  = (idx & 31) << 2;
            float4 vv = *(const float4*)(vbase + (size_t)(j0 + r) * (NHKV * HD) + dc);
            unsigned* dst = Vs + r * VSTR + dc;
            dst[0] = f2tf32(vv.x); dst[1] = f2tf32(vv.y);
            dst[2] = f2tf32(vv.z); dst[3] = f2tf32(vv.w);
        }
        __syncthreads();

        float sacc[8][4] = {};
        #pragma unroll
        for (int kc = 0; kc < 16; kc++) {
            int kb = kc << 3;
            unsigned qa[4];
            qa[0] = Qs[(mrow + g    ) * QSTR + kb + t];
            qa[1] = Qs[(mrow + g + 8) * QSTR + kb + t];
            qa[2] = Qs[(mrow + g    ) * QSTR + kb + t + 4];
            qa[3] = Qs[(mrow + g + 8) * QSTR + kb + t + 4];
            unsigned bb[8][2];
            #pragma unroll
            for (int ni = 0; ni < 8; ni++) {
                bb[ni][0] = KsT[(kb + t    ) * KSTR + (ni << 3) + g];
                bb[ni][1] = KsT[(kb + t + 4) * KSTR + (ni << 3) + g];
            }
            #pragma unroll
            for (int ni = 0; ni < 8; ni++)
                mma_tf32(sacc[ni], qa, bb[ni]);
        }

        float mx_lo = -1e30f, mx_hi = -1e30f;
        #pragma unroll
        for (int ni = 0; ni < 8; ni++) {
            int c0 = j0 + (ni << 3) + (t << 1);
            int c1 = c0 + 1;
            if (!((c0 <= qi_lo) && (c0 > qi_lo - WIN))) sacc[ni][0] = -1e30f;
            if (!((c1 <= qi_lo) && (c1 > qi_lo - WIN))) sacc[ni][1] = -1e30f;
            if (!((c0 <= qi_hi) && (c0 > qi_hi - WIN))) sacc[ni][2] = -1e30f;
            if (!((c1 <= qi_hi) && (c1 > qi_hi - WIN))) sacc[ni][3] = -1e30f;
            mx_lo = fmaxf(mx_lo, fmaxf(sacc[ni][0], sacc[ni][1]));
            mx_hi = fmaxf(mx_hi, fmaxf(sacc[ni][2], sacc[ni][3]));
        }
        mx_lo = fmaxf(mx_lo, __shfl_xor_sync(0xffffffffu, mx_lo, 1));
        mx_lo = fmaxf(mx_lo, __shfl_xor_sync(0xffffffffu, mx_lo, 2));
        mx_hi = fmaxf(mx_hi, __shfl_xor_sync(0xffffffffu, mx_hi, 1));
        mx_hi = fmaxf(mx_hi, __shfl_xor_sync(0xffffffffu, mx_hi, 2));

        float mnl = fmaxf(m_lo, mx_lo);
        float mnh = fmaxf(m_hi, mx_hi);
        float cl  = __expf(m_lo - mnl);
        float ch  = __expf(m_hi - mnh);
        m_lo = mnl; m_hi = mnh;

        float ps_lo = 0.f, ps_hi = 0.f;
        unsigned pf[8][4];
        #pragma unroll
        for (int ni = 0; ni < 8; ni++) {
            float p0 = (sacc[ni][0] > -1e29f) ? __expf(sacc[ni][0] - mnl) : 0.f;
            float p1 = (sacc[ni][1] > -1e29f) ? __expf(sacc[ni][1] - mnl) : 0.f;
            float p2 = (sacc[ni][2] > -1e29f) ? __expf(sacc[ni][2] - mnh) : 0.f;
            float p3 = (sacc[ni][3] > -1e29f) ? __expf(sacc[ni][3] - mnh) : 0.f;
            ps_lo += p0 + p1;
            ps_hi += p2 + p3;
            pf[ni][0] = f2tf32(p0); pf[ni][1] = f2tf32(p1);
            pf[ni][2] = f2tf32(p2); pf[ni][3] = f2tf32(p3);
        }
        ps_lo += __shfl_xor_sync(0xffffffffu, ps_lo, 1);
        ps_lo += __shfl_xor_sync(0xffffffffu, ps_lo, 2);
        ps_hi += __shfl_xor_sync(0xffffffffu, ps_hi, 1);
        ps_hi += __shfl_xor_sync(0xffffffffu, ps_hi, 2);
        l_lo = l_lo * cl + ps_lo;
        l_hi = l_hi * ch + ps_hi;

        #pragma unroll
        for (int n2 = 0; n2 < 16; n2++) {
            oacc[n2][0] *= cl; oacc[n2][1] *= cl;
            oacc[n2][2] *= ch; oacc[n2][3] *= ch;
        }

        #pragma unroll
        for (int kc = 0; kc < 8; kc++) {
            unsigned e0 = __shfl_sync(0xffffffffu, pf[kc][0], src0);
            unsigned o0 = __shfl_sync(0xffffffffu, pf[kc][1], src0);
            unsigned e1 = __shfl_sync(0xffffffffu, pf[kc][0], src1);
            unsigned o1 = __shfl_sync(0xffffffffu, pf[kc][1], src1);
            unsigned e2 = __shfl_sync(0xffffffffu, pf[kc][2], src0);
            unsigned o2 = __shfl_sync(0xffffffffu, pf[kc][3], src0);
            unsigned e3 = __shfl_sync(0xffffffffu, pf[kc][2], src1);
            unsigned o3 = __shfl_sync(0xffffffffu, pf[kc][3], src1);
            unsigned af[4];
            af[0] = odd ? o0 : e0;
            af[1] = odd ? o2 : e2;
            af[2] = odd ? o1 : e1;
            af[3] = odd ? o3 : e3;
            int kb = kc << 3;
            #pragma unroll
            for (int n2 = 0; n2 < 16; n2++) {
                unsigned bb2[2];
                bb2[0] = Vs[(kb + t    ) * VSTR + (n2 << 3) + g];
                bb2[1] = Vs[(kb + t + 4) * VSTR + (n2 << 3) + g];
                mma_tf32(oacc[n2], af, bb2);
            }
        }
    }

    float il = 1.0f / l_lo;
    float ih = 1.0f / l_hi;
    float* obase = o + (size_t)b * SEQ * (NHQ * HD) + h * HD;
    int rlo = q0 + mrow + g;
    int rhi = rlo + 8;
    #pragma unroll
    for (int n2 = 0; n2 < 16; n2++) {
        int dn = (n2 << 3) + (t << 1);
        *(float2*)(obase + (size_t)rlo * (NHQ * HD) + dn) =
            make_float2(oacc[n2][0] * il, oacc[n2][1] * il);
        *(float2*)(obase + (size_t)rhi * (NHQ * HD) + dn) =
            make_float2(oacc[n2][2] * ih, oacc[n2][3] * ih);
    }
}

// ---------------------------------------------------------------------------
extern "C" void kernel_launch(void* const* d_in, const int* in_sizes, int n_in,
                              void* d_out, int out_size)
{
    const float* hidden = (const float*)d_in[0];
    const float* wq = (const float*)d_in[1];
    const float* wk = (const float*)d_in[2];
    const float* wv = (const float*)d_in[3];
    const float* wo = (const float*)d_in[4];
    const float* qw = (const float*)d_in[5];
    const float* kw = (const float*)d_in[6];
    float* out = (float*)d_out;

    float *q, *k, *v, *attn, *ct, *st;
    cudaGetSymbolAddress((void**)&q,    g_q);
    cudaGetSymbolAddress((void**)&k,    g_k);
    cudaGetSymbolAddress((void**)&v,    g_v);
    cudaGetSymbolAddress((void**)&attn, g_attn);
    cudaGetSymbolAddress((void**)&ct,   g_rope_cos);
    cudaGetSymbolAddress((void**)&st,   g_rope_sin);

    cudaFuncSetAttribute(flash_tf32, cudaFuncAttributeMaxDynamicSharedMemorySize,
                         FLASH_BYTES);
    cudaFuncSetAttribute(gemm_qkv, cudaFuncAttributeMaxDynamicSharedMemorySize,
                         GEMM_SMEM);
    cudaFuncSetAttribute(gemm_o, cudaFuncAttributeMaxDynamicSharedMemorySize,
                         GEMM_SMEM);

    // launch 0: rope tables
    rope_table<<<(SEQ*64 + 255) / 256, 256>>>(ct, st);
    // launch 1: fused QKV projection
    gemm_qkv<<<dim3(32, MROWS/128), 256, GEMM_SMEM>>>(hidden, wq, wk, wv, q, k, v);
    // launch 2: fused norm+rope for q and k
    {
        int warps = MROWS * (NHQ + NHKV);
        norm_rope_both<<<(warps*32 + 255) / 256, 256>>>(q, qw, k, kw, ct, st);
    }
    // launch 3: flash attention  (profiled slot)
    flash_tf32<<<dim3(SEQ/FBQ, NHQ, NB), 256, FLASH_BYTES>>>(q, k, v, attn);
    // launch 4: output projection
    gemm_o<<<dim3(HID/128, MROWS/128), 256, GEMM_SMEM>>>(attn, wo, out);
}